// round 1
// baseline (speedup 1.0000x reference)
#include <cuda_runtime.h>
#include <math.h>

#define BB 8
#define NN 4096
#define DIM 1024

// Scratch (no allocation allowed)
__device__ float g_q0[BB * DIM];       // [B, DIM]
__device__ float g_v[BB * DIM];        // [B, DIM]
__device__ float g_scores[BB * NN];    // [B, N]

__device__ __forceinline__ float warp_sum(float v) {
#pragma unroll
    for (int off = 16; off > 0; off >>= 1)
        v += __shfl_down_sync(0xFFFFFFFFu, v, off);
    return v;
}

// ---------------------------------------------------------------------------
// Kernel 1: q0[b,e] = dot(Wq[e,:], x[b,0,:]) + bq[e];  also zero g_v.
// grid 16 blocks x 256 threads; block handles 64 e-values (warp: 8 e each).
// ---------------------------------------------------------------------------
__global__ void __launch_bounds__(256) k_q0(const float* __restrict__ x,
                                            const float* __restrict__ Wq,
                                            const float* __restrict__ bq) {
    __shared__ float xs[BB][DIM];  // 32 KB
    int tid = threadIdx.x;

    // zero g_v (8192 floats; 16*256 = 4096 threads -> 2 each)
    int gt = blockIdx.x * 256 + tid;
    g_v[gt] = 0.0f;
    g_v[gt + 4096] = 0.0f;

    // load x[b,0,:] for all b
    for (int i = tid; i < BB * DIM; i += 256) {
        int b = i >> 10;
        int d = i & (DIM - 1);
        xs[b][d] = x[(size_t)b * NN * DIM + d];
    }
    __syncthreads();

    int warp = tid >> 5, lane = tid & 31;
#pragma unroll
    for (int ew = 0; ew < 8; ew++) {
        int e = blockIdx.x * 64 + warp * 8 + ew;
        const float* wrow = Wq + (size_t)e * DIM;
        float acc[BB];
#pragma unroll
        for (int b = 0; b < BB; b++) acc[b] = 0.0f;

        for (int i = lane; i < DIM; i += 32) {
            float w = wrow[i];
#pragma unroll
            for (int b = 0; b < BB; b++) acc[b] += w * xs[b][i];
        }
#pragma unroll
        for (int b = 0; b < BB; b++) acc[b] = warp_sum(acc[b]);
        if (lane == 0) {
            float bias = bq[e];
#pragma unroll
            for (int b = 0; b < BB; b++) g_q0[b * DIM + e] = acc[b] + bias;
        }
    }
}

// ---------------------------------------------------------------------------
// Kernel 2: v[b,d] += sum_{e in chunk} q0[b,e] * Wk[e,d]
// grid (8 d-tiles, 16 e-chunks) x 128 threads. Coalesced Wk reads, atomicAdd.
// ---------------------------------------------------------------------------
__global__ void __launch_bounds__(128) k_v(const float* __restrict__ Wk) {
    __shared__ float q0s[BB][64];
    int t = threadIdx.x;
    int d = blockIdx.x * 128 + t;
    int e0 = blockIdx.y * 64;

    for (int i = t; i < BB * 64; i += 128) {
        int b = i >> 6;
        int j = i & 63;
        q0s[b][j] = g_q0[b * DIM + e0 + j];
    }
    __syncthreads();

    float acc[BB];
#pragma unroll
    for (int b = 0; b < BB; b++) acc[b] = 0.0f;

#pragma unroll 8
    for (int j = 0; j < 64; j++) {
        float w = Wk[(size_t)(e0 + j) * DIM + d];
#pragma unroll
        for (int b = 0; b < BB; b++) acc[b] += q0s[b][j] * w;
    }
#pragma unroll
    for (int b = 0; b < BB; b++) atomicAdd(&g_v[b * DIM + d], acc[b]);
}

// ---------------------------------------------------------------------------
// Kernel 3 (heavy pass): scores[b,m] = dot(x[b,m,:], v[b,:])
// grid (N/8, B) x 256 threads. One warp per row m; v[b] cached in smem.
// ---------------------------------------------------------------------------
__global__ void __launch_bounds__(256) k_scores(const float* __restrict__ x) {
    __shared__ float4 vs[DIM / 4];  // 4 KB
    int b = blockIdx.y;
    int tid = threadIdx.x;

    const float4* vg = (const float4*)(g_v + b * DIM);
    if (tid < DIM / 4) vs[tid] = vg[tid];
    __syncthreads();

    int warp = tid >> 5, lane = tid & 31;
    int m = blockIdx.x * 8 + warp;

    const float4* xr = (const float4*)(x + ((size_t)b * NN + m) * DIM);
    float acc = 0.0f;
#pragma unroll
    for (int i = 0; i < 8; i++) {
        float4 xv = xr[lane + 32 * i];
        float4 vv = vs[lane + 32 * i];
        acc += xv.x * vv.x + xv.y * vv.y + xv.z * vv.z + xv.w * vv.w;
    }
    acc = warp_sum(acc);
    if (lane == 0) g_scores[b * NN + m] = acc;
}

// ---------------------------------------------------------------------------
// Kernel 4: per-batch softmax over N=4096. 1 block of 1024 threads per batch.
// ---------------------------------------------------------------------------
__global__ void __launch_bounds__(1024) k_softmax(float* __restrict__ out) {
    __shared__ float red[32];
    __shared__ float bcast;
    int b = blockIdx.x;
    int t = threadIdx.x;
    int warp = t >> 5, lane = t & 31;

    float s[4];
#pragma unroll
    for (int i = 0; i < 4; i++) s[i] = g_scores[b * NN + t + i * 1024];

    // block max
    float m = fmaxf(fmaxf(s[0], s[1]), fmaxf(s[2], s[3]));
#pragma unroll
    for (int off = 16; off > 0; off >>= 1)
        m = fmaxf(m, __shfl_down_sync(0xFFFFFFFFu, m, off));
    if (lane == 0) red[warp] = m;
    __syncthreads();
    if (warp == 0) {
        float v = red[lane];
#pragma unroll
        for (int off = 16; off > 0; off >>= 1)
            v = fmaxf(v, __shfl_down_sync(0xFFFFFFFFu, v, off));
        if (lane == 0) bcast = v;
    }
    __syncthreads();
    float M = bcast;

    float e[4];
    float local = 0.0f;
#pragma unroll
    for (int i = 0; i < 4; i++) {
        e[i] = expf(s[i] - M);
        local += e[i];
    }
    local = warp_sum(local);
    if (lane == 0) red[warp] = local;
    __syncthreads();
    if (warp == 0) {
        float v = red[lane];
        v = warp_sum(v);
        if (lane == 0) bcast = v;
    }
    __syncthreads();
    float inv = 1.0f / bcast;

#pragma unroll
    for (int i = 0; i < 4; i++)
        out[b * NN + t + i * 1024] = e[i] * inv;
}

extern "C" void kernel_launch(void* const* d_in, const int* in_sizes, int n_in,
                              void* d_out, int out_size) {
    const float* x  = (const float*)d_in[0];
    const float* Wq = (const float*)d_in[1];
    const float* bq = (const float*)d_in[2];
    const float* Wk = (const float*)d_in[3];
    // bk (d_in[4]) is mathematically dead: it shifts every score in a row by
    // the same constant, which cancels in softmax.
    float* out = (float*)d_out;

    k_q0<<<16, 256>>>(x, Wq, bq);
    k_v<<<dim3(8, 16), 128>>>(Wk);
    k_scores<<<dim3(NN / 8, BB), 256>>>(x);
    k_softmax<<<BB, 1024>>>(out);
}

// round 4
// speedup vs baseline: 1.4757x; 1.4757x over previous
#include <cuda_runtime.h>
#include <math.h>

#define BB 8
#define NN 4096
#define DIM 1024

// Scratch (no allocation allowed)
__device__ float g_q0[BB * DIM];       // [B, DIM]
__device__ float g_v[BB * DIM];        // [B, DIM]
__device__ float g_scores[BB * NN];    // [B, N]
__device__ unsigned int g_ticket;      // monotonic across graph replays

__device__ __forceinline__ float warp_sum(float v) {
#pragma unroll
    for (int off = 16; off > 0; off >>= 1)
        v += __shfl_down_sync(0xFFFFFFFFu, v, off);
    return v;
}

// ---------------------------------------------------------------------------
// Kernel 1: q0[b,e] = dot(Wq[e,:], x[b,0,:]) + bq[e];  also zero g_v.
// 128 blocks x 256 threads; one e-row per warp -> Wq streamed chip-wide.
// ---------------------------------------------------------------------------
__global__ void __launch_bounds__(256) k_q0(const float* __restrict__ x,
                                            const float* __restrict__ Wq,
                                            const float* __restrict__ bq) {
    __shared__ float xs[BB][DIM];  // 32 KB
    int tid = threadIdx.x;

    // zero g_v (8192 floats; 128*256 = 32768 threads)
    int gt = blockIdx.x * 256 + tid;
    if (gt < BB * DIM) g_v[gt] = 0.0f;

    // load x[b,0,:] for all b (first wave DRAM, then L2 broadcast)
    for (int i = tid; i < BB * DIM; i += 256) {
        int b = i >> 10;
        int d = i & (DIM - 1);
        xs[b][d] = x[(size_t)b * NN * DIM + d];
    }
    __syncthreads();

    int warp = tid >> 5, lane = tid & 31;
    int e = blockIdx.x * 8 + warp;
    const float* wrow = Wq + (size_t)e * DIM;

    float acc[BB];
#pragma unroll
    for (int b = 0; b < BB; b++) acc[b] = 0.0f;

#pragma unroll 4
    for (int i = lane; i < DIM; i += 32) {
        float w = wrow[i];
#pragma unroll
        for (int b = 0; b < BB; b++) acc[b] += w * xs[b][i];
    }
#pragma unroll
    for (int b = 0; b < BB; b++) acc[b] = warp_sum(acc[b]);
    if (lane == 0) {
        float bias = bq[e];
#pragma unroll
        for (int b = 0; b < BB; b++) g_q0[b * DIM + e] = acc[b] + bias;
    }
}

// ---------------------------------------------------------------------------
// Kernel 2: v[b,d] += sum_{e in chunk} q0[b,e] * Wk[e,d]
// grid (8 d-tiles, 16 e-chunks) x 128 threads. Coalesced Wk reads, atomicAdd.
// ---------------------------------------------------------------------------
__global__ void __launch_bounds__(128) k_v(const float* __restrict__ Wk) {
    __shared__ float q0s[BB][64];
    int t = threadIdx.x;
    int d = blockIdx.x * 128 + t;
    int e0 = blockIdx.y * 64;

    for (int i = t; i < BB * 64; i += 128) {
        int b = i >> 6;
        int j = i & 63;
        q0s[b][j] = g_q0[b * DIM + e0 + j];
    }
    __syncthreads();

    float acc[BB];
#pragma unroll
    for (int b = 0; b < BB; b++) acc[b] = 0.0f;

#pragma unroll 8
    for (int j = 0; j < 64; j++) {
        float w = Wk[(size_t)(e0 + j) * DIM + d];
#pragma unroll
        for (int b = 0; b < BB; b++) acc[b] += q0s[b][j] * w;
    }
#pragma unroll
    for (int b = 0; b < BB; b++) atomicAdd(&g_v[b * DIM + d], acc[b]);
}

// ---------------------------------------------------------------------------
// Kernel 3 (heavy pass + fused softmax):
//   scores[b,m] = dot(x[b,m,:], v[b,:]);  last 8 ticket-holders do softmax.
// grid (128, 8) x 512 threads. 16 warps/block, 2 rows per warp (MLP=16).
// ---------------------------------------------------------------------------
#define SBLK 1024  // total blocks = 128 * 8

__global__ void __launch_bounds__(512) k_scores(const float* __restrict__ x,
                                                float* __restrict__ out) {
    __shared__ float4 vs[DIM / 4];  // 4 KB
    __shared__ float red[16];
    __shared__ float bcast;
    __shared__ unsigned int s_ticket;

    int b = blockIdx.y;
    int tid = threadIdx.x;

    const float4* vg = (const float4*)(g_v + b * DIM);
    if (tid < DIM / 4) vs[tid] = vg[tid];
    __syncthreads();

    int warp = tid >> 5, lane = tid & 31;
    int m0 = blockIdx.x * 32 + warp * 2;

    const float4* xr0 = (const float4*)(x + ((size_t)b * NN + m0) * DIM);
    const float4* xr1 = xr0 + DIM / 4;
    float a0 = 0.0f, a1 = 0.0f;
#pragma unroll
    for (int i = 0; i < 8; i++) {
        float4 u0 = xr0[lane + 32 * i];
        float4 u1 = xr1[lane + 32 * i];
        float4 vv = vs[lane + 32 * i];
        a0 += u0.x * vv.x + u0.y * vv.y + u0.z * vv.z + u0.w * vv.w;
        a1 += u1.x * vv.x + u1.y * vv.y + u1.z * vv.z + u1.w * vv.w;
    }
    a0 = warp_sum(a0);
    a1 = warp_sum(a1);
    if (lane == 0) {
        g_scores[b * NN + m0] = a0;
        g_scores[b * NN + m0 + 1] = a1;
    }

    // publish scores, take a ticket
    __threadfence();
    __syncthreads();
    if (tid == 0) s_ticket = atomicAdd(&g_ticket, 1u);
    __syncthreads();
    unsigned int t = s_ticket;
    unsigned int tt = t % SBLK;
    if (tt < SBLK - 8) return;

    // last 8 tickets: wait for all blocks of THIS replay, then softmax 1 batch
    unsigned int target = (t / SBLK + 1u) * SBLK;
    if (tid == 0) {
        while (atomicAdd(&g_ticket, 0u) < target) {}
    }
    __syncthreads();
    __threadfence();

    int sb = (int)(tt - (SBLK - 8));  // batch 0..7

    // softmax over 4096 values, 512 threads * 8 each; read via L2 (__ldcg)
    float s[8];
#pragma unroll
    for (int i = 0; i < 8; i++)
        s[i] = __ldcg(&g_scores[sb * NN + tid + i * 512]);

    float m = s[0];
#pragma unroll
    for (int i = 1; i < 8; i++) m = fmaxf(m, s[i]);
#pragma unroll
    for (int off = 16; off > 0; off >>= 1)
        m = fmaxf(m, __shfl_down_sync(0xFFFFFFFFu, m, off));
    if (lane == 0) red[warp] = m;
    __syncthreads();
    if (warp == 0) {
        float v = (lane < 16) ? red[lane] : -1e30f;
#pragma unroll
        for (int off = 16; off > 0; off >>= 1)
            v = fmaxf(v, __shfl_down_sync(0xFFFFFFFFu, v, off));
        if (lane == 0) bcast = v;
    }
    __syncthreads();
    float M = bcast;

    float e[8];
    float local = 0.0f;
#pragma unroll
    for (int i = 0; i < 8; i++) {
        e[i] = expf(s[i] - M);
        local += e[i];
    }
    local = warp_sum(local);
    if (lane == 0) red[warp] = local;
    __syncthreads();
    if (warp == 0) {
        float v = (lane < 16) ? red[lane] : 0.0f;
        v = warp_sum(v);
        if (lane == 0) bcast = v;
    }
    __syncthreads();
    float inv = 1.0f / bcast;

#pragma unroll
    for (int i = 0; i < 8; i++)
        out[sb * NN + tid + i * 512] = e[i] * inv;
}

extern "C" void kernel_launch(void* const* d_in, const int* in_sizes, int n_in,
                              void* d_out, int out_size) {
    const float* x  = (const float*)d_in[0];
    const float* Wq = (const float*)d_in[1];
    const float* bq = (const float*)d_in[2];
    const float* Wk = (const float*)d_in[3];
    // bk (d_in[4]) is mathematically dead: it shifts every score in a row by
    // the same constant, which cancels in softmax.
    float* out = (float*)d_out;

    k_q0<<<128, 256>>>(x, Wq, bq);
    k_v<<<dim3(8, 16), 128>>>(Wk);
    k_scores<<<dim3(128, 8), 512>>>(x, out);
}

// round 7
// speedup vs baseline: 1.7982x; 1.2186x over previous
#include <cuda_runtime.h>
#include <math.h>

#define BB 8
#define NN 4096
#define DIM 1024

// Scratch (no allocation allowed)
__device__ float g_q0[BB * DIM];       // [B, DIM]
__device__ float g_v[BB * DIM];        // [B, DIM]
__device__ float g_scores[BB * NN];    // [B, N]
__device__ unsigned int g_bar;         // prepass grid barrier (monotonic)
__device__ unsigned int g_ticket;      // scores/softmax ticket (monotonic)

__device__ __forceinline__ float warp_sum(float v) {
#pragma unroll
    for (int off = 16; off > 0; off >>= 1)
        v += __shfl_down_sync(0xFFFFFFFFu, v, off);
    return v;
}

// ---------------------------------------------------------------------------
// Fused prepass: phase 1 computes q0 = Wq@x0 + bq (and zeroes g_v),
// grid barrier, phase 2 computes v = q0@Wk via atomics.
// 128 blocks x 256 threads (all resident: 128 < 148 SMs).
// ---------------------------------------------------------------------------
#define PBLK 128

__global__ void __launch_bounds__(256) k_prepass(const float* __restrict__ x,
                                                 const float* __restrict__ Wq,
                                                 const float* __restrict__ bq,
                                                 const float* __restrict__ Wk) {
    __shared__ float4 xs4[BB][DIM / 4];  // 32 KB (phase 1); reused in phase 2
    __shared__ unsigned int s_tk;
    int tid = threadIdx.x;
    int bx = blockIdx.x;

    // ---- phase 1: q0 ----
    // zero g_v (8192 floats over 32768 threads)
    int gt = bx * 256 + tid;
    if (gt < BB * DIM) g_v[gt] = 0.0f;

    // stage x[b,0,:] for all b as float4, MLP=8
#pragma unroll
    for (int j = 0; j < 8; j++) {
        int idx = tid + 256 * j;            // 0..2047 float4
        int b = idx >> 8;                   // 256 float4 per row
        int d4 = idx & 255;
        const float4* xsrc = (const float4*)(x + (size_t)b * NN * DIM);
        xs4[b][d4] = xsrc[d4];
    }
    __syncthreads();

    int warp = tid >> 5, lane = tid & 31;
    int e = bx * 8 + warp;
    const float4* wrow4 = (const float4*)(Wq + (size_t)e * DIM);

    float acc[BB];
#pragma unroll
    for (int b = 0; b < BB; b++) acc[b] = 0.0f;

#pragma unroll
    for (int j = 0; j < 8; j++) {
        int i = lane + 32 * j;
        float4 w4 = wrow4[i];
#pragma unroll
        for (int b = 0; b < BB; b++) {
            float4 x4 = xs4[b][i];
            acc[b] += w4.x * x4.x + w4.y * x4.y + w4.z * x4.z + w4.w * x4.w;
        }
    }
#pragma unroll
    for (int b = 0; b < BB; b++) acc[b] = warp_sum(acc[b]);
    if (lane == 0) {
        float bias = bq[e];
#pragma unroll
        for (int b = 0; b < BB; b++) g_q0[b * DIM + e] = acc[b] + bias;
    }

    // ---- grid barrier (monotonic across graph replays) ----
    __threadfence();
    __syncthreads();
    if (tid == 0) s_tk = atomicAdd(&g_bar, 1u);
    __syncthreads();
    unsigned int target = (s_tk / PBLK + 1u) * PBLK;
    if (tid == 0) {
        while (atomicAdd(&g_bar, 0u) < target) {}
    }
    __syncthreads();
    __threadfence();

    // ---- phase 2: v[b,d] += sum_{e chunk} q0[b,e] * Wk[e,d] ----
    // 4 d-tiles (256 each) x 32 e-chunks (32 each) = 128 blocks
    int dt = bx & 3;
    int e0 = (bx >> 2) * 32;
    int d = dt * 256 + tid;

    float* qs = (float*)xs4;  // BB*32 floats
    if (tid < BB * 32) {
        int b = tid >> 5, j = tid & 31;
        qs[b * 32 + j] = g_q0[b * DIM + e0 + j];
    }
    __syncthreads();

    float vacc[BB];
#pragma unroll
    for (int b = 0; b < BB; b++) vacc[b] = 0.0f;

#pragma unroll 8
    for (int j = 0; j < 32; j++) {
        float w = Wk[(size_t)(e0 + j) * DIM + d];
#pragma unroll
        for (int b = 0; b < BB; b++) vacc[b] += qs[b * 32 + j] * w;
    }
#pragma unroll
    for (int b = 0; b < BB; b++) atomicAdd(&g_v[b * DIM + d], vacc[b]);
}

// ---------------------------------------------------------------------------
// Heavy pass + fused softmax:
//   scores[b,m] = dot(x[b,m,:], v[b,:]);  last 8 ticket-holders do softmax.
// grid (128, 8) x 512 threads. 16 warps/block, 2 rows per warp (MLP=16).
// ---------------------------------------------------------------------------
#define SBLK 1024  // total blocks = 128 * 8

__global__ void __launch_bounds__(512) k_scores(const float* __restrict__ x,
                                                float* __restrict__ out) {
    __shared__ float4 vs[DIM / 4];  // 4 KB
    __shared__ float red[16];
    __shared__ float bcast;
    __shared__ unsigned int s_ticket;

    int b = blockIdx.y;
    int tid = threadIdx.x;

    const float4* vg = (const float4*)(g_v + b * DIM);
    if (tid < DIM / 4) vs[tid] = vg[tid];
    __syncthreads();

    int warp = tid >> 5, lane = tid & 31;
    int m0 = blockIdx.x * 32 + warp * 2;

    const float4* xr0 = (const float4*)(x + ((size_t)b * NN + m0) * DIM);
    const float4* xr1 = xr0 + DIM / 4;
    float a0 = 0.0f, a1 = 0.0f;
#pragma unroll
    for (int i = 0; i < 8; i++) {
        float4 u0 = xr0[lane + 32 * i];
        float4 u1 = xr1[lane + 32 * i];
        float4 vv = vs[lane + 32 * i];
        a0 += u0.x * vv.x + u0.y * vv.y + u0.z * vv.z + u0.w * vv.w;
        a1 += u1.x * vv.x + u1.y * vv.y + u1.z * vv.z + u1.w * vv.w;
    }
    a0 = warp_sum(a0);
    a1 = warp_sum(a1);
    if (lane == 0) {
        g_scores[b * NN + m0] = a0;
        g_scores[b * NN + m0 + 1] = a1;
    }

    // publish scores, take a ticket
    __threadfence();
    __syncthreads();
    if (tid == 0) s_ticket = atomicAdd(&g_ticket, 1u);
    __syncthreads();
    unsigned int t = s_ticket;
    unsigned int tt = t % SBLK;
    if (tt < SBLK - 8) return;

    // last 8 tickets: wait for all blocks of THIS replay, then softmax 1 batch
    unsigned int target = (t / SBLK + 1u) * SBLK;
    if (tid == 0) {
        while (atomicAdd(&g_ticket, 0u) < target) {}
    }
    __syncthreads();
    __threadfence();

    int sb = (int)(tt - (SBLK - 8));  // batch 0..7

    // softmax over 4096 values, 512 threads * 8 each; read via L2 (__ldcg)
    float s[8];
#pragma unroll
    for (int i = 0; i < 8; i++)
        s[i] = __ldcg(&g_scores[sb * NN + tid + i * 512]);

    float m = s[0];
#pragma unroll
    for (int i = 1; i < 8; i++) m = fmaxf(m, s[i]);
#pragma unroll
    for (int off = 16; off > 0; off >>= 1)
        m = fmaxf(m, __shfl_down_sync(0xFFFFFFFFu, m, off));
    if (lane == 0) red[warp] = m;
    __syncthreads();
    if (warp == 0) {
        float v = (lane < 16) ? red[lane] : -1e30f;
#pragma unroll
        for (int off = 16; off > 0; off >>= 1)
            v = fmaxf(v, __shfl_down_sync(0xFFFFFFFFu, v, off));
        if (lane == 0) bcast = v;
    }
    __syncthreads();
    float M = bcast;

    float e[8];
    float local = 0.0f;
#pragma unroll
    for (int i = 0; i < 8; i++) {
        e[i] = expf(s[i] - M);
        local += e[i];
    }
    local = warp_sum(local);
    if (lane == 0) red[warp] = local;
    __syncthreads();
    if (warp == 0) {
        float v = (lane < 16) ? red[lane] : 0.0f;
        v = warp_sum(v);
        if (lane == 0) bcast = v;
    }
    __syncthreads();
    float inv = 1.0f / bcast;

#pragma unroll
    for (int i = 0; i < 8; i++)
        out[sb * NN + tid + i * 512] = e[i] * inv;
}

extern "C" void kernel_launch(void* const* d_in, const int* in_sizes, int n_in,
                              void* d_out, int out_size) {
    const float* x  = (const float*)d_in[0];
    const float* Wq = (const float*)d_in[1];
    const float* bq = (const float*)d_in[2];
    const float* Wk = (const float*)d_in[3];
    // bk (d_in[4]) is mathematically dead: it shifts every score in a row by
    // the same constant, which cancels in softmax.
    float* out = (float*)d_out;

    k_prepass<<<PBLK, 256>>>(x, Wq, bq, Wk);
    k_scores<<<dim3(128, 8), 512>>>(x, out);
}

// round 9
// speedup vs baseline: 1.9984x; 1.1113x over previous
#include <cuda_runtime.h>
#include <math.h>

#define BB 8
#define NN 4096
#define DIM 1024
#define GRID 296            // 148 SMs x 2 CTAs, all resident (occ-safe)
#define WARPS (GRID * 16)   // 4736

// Scratch (no allocation allowed)
__device__ float g_q0[BB * DIM];
__device__ float g_v[BB * DIM];
__device__ float g_scores[BB * NN];
__device__ unsigned int g_b1, g_b2, g_b3;  // monotonic barrier counters

__device__ __forceinline__ float warp_sum(float v) {
#pragma unroll
    for (int off = 16; off > 0; off >>= 1)
        v += __shfl_down_sync(0xFFFFFFFFu, v, off);
    return v;
}

// Monotonic grid barrier: safe across graph replays (counter never resets).
__device__ __forceinline__ void grid_barrier(unsigned int* ctr) {
    __shared__ unsigned int s_tk;
    __threadfence();
    __syncthreads();
    if (threadIdx.x == 0) s_tk = atomicAdd(ctr, 1u);
    __syncthreads();
    unsigned int target = (s_tk / GRID + 1u) * GRID;
    if (threadIdx.x == 0) {
        while (atomicAdd(ctr, 0u) < target) __nanosleep(32);
    }
    __syncthreads();
    __threadfence();
}

__global__ void __launch_bounds__(512, 2)
k_fused(const float* __restrict__ x, const float* __restrict__ Wq,
        const float* __restrict__ bq, const float* __restrict__ Wk,
        float* __restrict__ out) {
    __shared__ float4 buf4[BB * DIM / 4];  // 32 KB: xs (ph1) / vs (ph3)
    __shared__ float qs[BB][32];           // 1 KB  (ph2)
    __shared__ float red[16];
    __shared__ float bcast;

    int tid = threadIdx.x;
    int bx = blockIdx.x;
    int warp = tid >> 5, lane = tid & 31;

    // ================= Phase 1: q0[b,e] = Wq[e,:]·x[b,0,:] + bq[e] ========
    // blocks 0..15 zero g_v; blocks 0..63 compute q0 (one e-row per warp).
    if (bx < 16) {
        int gt = bx * 512 + tid;
        g_v[gt] = 0.0f;
    }
    if (bx < 64) {
        // stage x[b,0,:] for all b: 2048 float4, MLP=4x512 threads
#pragma unroll
        for (int j = 0; j < 4; j++) {
            int idx = tid + 512 * j;
            int b = idx >> 8, d4 = idx & 255;
            buf4[idx] = ((const float4*)x)[(size_t)b * (NN * DIM / 4) + d4];
        }
        __syncthreads();

        int e = bx * 16 + warp;  // 0..1023
        const float4* wrow4 = (const float4*)Wq + (size_t)e * 256;
        float acc[BB];
#pragma unroll
        for (int b = 0; b < BB; b++) acc[b] = 0.0f;
#pragma unroll
        for (int j = 0; j < 8; j++) {
            int i = lane + 32 * j;
            float4 w4 = wrow4[i];
#pragma unroll
            for (int b = 0; b < BB; b++) {
                float4 x4 = buf4[b * 256 + i];
                acc[b] += w4.x * x4.x + w4.y * x4.y + w4.z * x4.z + w4.w * x4.w;
            }
        }
#pragma unroll
        for (int b = 0; b < BB; b++) acc[b] = warp_sum(acc[b]);
        if (lane == 0) {
            float bias = bq[e];
#pragma unroll
            for (int b = 0; b < BB; b++) g_q0[b * DIM + e] = acc[b] + bias;
        }
    }

    grid_barrier(&g_b1);

    // ================= Phase 2: v[b,d] += q0[b,e-chunk]·Wk[e-chunk,d] =====
    // 64 blocks: 32 e-chunks (32 e each) x 2 d-halves (512 d each).
    if (bx < 64) {
        int e0 = (bx >> 1) * 32;
        int d = (bx & 1) * 512 + tid;
        if (tid < 256) {
            int b = tid >> 5, j = tid & 31;
            qs[b][j] = __ldcg(&g_q0[b * DIM + e0 + j]);
        }
        __syncthreads();

        float vacc[BB];
#pragma unroll
        for (int b = 0; b < BB; b++) vacc[b] = 0.0f;
#pragma unroll 8
        for (int j = 0; j < 32; j++) {
            float w = __ldg(&Wk[(size_t)(e0 + j) * DIM + d]);
#pragma unroll
            for (int b = 0; b < BB; b++) vacc[b] += qs[b][j] * w;
        }
#pragma unroll
        for (int b = 0; b < BB; b++) atomicAdd(&g_v[b * DIM + d], vacc[b]);
    }

    grid_barrier(&g_b2);

    // ================= Phase 3: scores[r] = x[r,:]·v[b(r),:] ==============
    // All 4736 warps; per-warp row stride (6-7 rows each, balanced).
#pragma unroll
    for (int j = 0; j < 4; j++) {
        int idx = tid + 512 * j;
        buf4[idx] = __ldcg((const float4*)g_v + idx);
    }
    __syncthreads();

    int gw = bx * 16 + warp;
    for (int r = gw; r < BB * NN; r += WARPS) {
        int b = r >> 12;
        const float4* xr4 = (const float4*)x + (size_t)r * 256;
        float acc = 0.0f;
#pragma unroll
        for (int j = 0; j < 8; j++) {
            int i = lane + 32 * j;
            float4 u = xr4[i];
            float4 vv = buf4[b * 256 + i];
            acc += u.x * vv.x + u.y * vv.y + u.z * vv.z + u.w * vv.w;
        }
        acc = warp_sum(acc);
        if (lane == 0) g_scores[r] = acc;
    }

    grid_barrier(&g_b3);

    // ================= Phase 4: softmax, blocks 0..7 ======================
    if (bx >= 8) return;
    int sb = bx;

    float s[8];
#pragma unroll
    for (int i = 0; i < 8; i++)
        s[i] = __ldcg(&g_scores[sb * NN + tid + i * 512]);

    float m = s[0];
#pragma unroll
    for (int i = 1; i < 8; i++) m = fmaxf(m, s[i]);
#pragma unroll
    for (int off = 16; off > 0; off >>= 1)
        m = fmaxf(m, __shfl_down_sync(0xFFFFFFFFu, m, off));
    if (lane == 0) red[warp] = m;
    __syncthreads();
    if (warp == 0) {
        float v = (lane < 16) ? red[lane] : -1e30f;
#pragma unroll
        for (int off = 16; off > 0; off >>= 1)
            v = fmaxf(v, __shfl_down_sync(0xFFFFFFFFu, v, off));
        if (lane == 0) bcast = v;
    }
    __syncthreads();
    float M = bcast;

    float e[8];
    float local = 0.0f;
#pragma unroll
    for (int i = 0; i < 8; i++) {
        e[i] = expf(s[i] - M);
        local += e[i];
    }
    local = warp_sum(local);
    if (lane == 0) red[warp] = local;
    __syncthreads();
    if (warp == 0) {
        float v = (lane < 16) ? red[lane] : 0.0f;
        v = warp_sum(v);
        if (lane == 0) bcast = v;
    }
    __syncthreads();
    float inv = 1.0f / bcast;

#pragma unroll
    for (int i = 0; i < 8; i++)
        out[sb * NN + tid + i * 512] = e[i] * inv;
}

extern "C" void kernel_launch(void* const* d_in, const int* in_sizes, int n_in,
                              void* d_out, int out_size) {
    const float* x  = (const float*)d_in[0];
    const float* Wq = (const float*)d_in[1];
    const float* bq = (const float*)d_in[2];
    const float* Wk = (const float*)d_in[3];
    // bk (d_in[4]) is mathematically dead: it shifts every score in a row by
    // the same constant, which cancels in softmax.
    float* out = (float*)d_out;

    k_fused<<<GRID, 512>>>(x, Wq, bq, Wk, out);
}

// round 10
// speedup vs baseline: 2.0147x; 1.0082x over previous
#include <cuda_runtime.h>
#include <math.h>

#define BB 8
#define NN 4096
#define DIM 1024
#define GRID 296            // 148 SMs x 2 CTAs, all resident
#define TOTAL_ROWS (BB * NN)
#define CHUNK 32            // rows per dynamic grab

// Scratch (no allocation allowed). Zero at load; re-zeroed at end of each run.
__device__ float g_q0[BB * DIM];
__device__ float g_v[BB * DIM];
__device__ float g_scores[BB * NN];
__device__ unsigned int g_b1, g_b2, g_b3;  // monotonic barrier counters
__device__ unsigned int g_row;             // phase-3 ticket (reset at end)

__device__ __forceinline__ float warp_sum(float v) {
#pragma unroll
    for (int off = 16; off > 0; off >>= 1)
        v += __shfl_down_sync(0xFFFFFFFFu, v, off);
    return v;
}

// Monotonic grid barrier: safe across graph replays (counter never resets).
__device__ __forceinline__ void grid_barrier(unsigned int* ctr) {
    __shared__ unsigned int s_tk;
    __threadfence();
    __syncthreads();
    if (threadIdx.x == 0) s_tk = atomicAdd(ctr, 1u);
    __syncthreads();
    unsigned int target = (s_tk / GRID + 1u) * GRID;
    if (threadIdx.x == 0) {
        while (atomicAdd(ctr, 0u) < target) __nanosleep(32);
    }
    __syncthreads();
    __threadfence();
}

__global__ void __launch_bounds__(512, 2)
k_fused(const float* __restrict__ x, const float* __restrict__ Wq,
        const float* __restrict__ bq, const float* __restrict__ Wk,
        float* __restrict__ out) {
    __shared__ float4 buf4[BB * DIM / 4];  // 32 KB: xs (ph1) / vs (ph3)
    __shared__ float qs[BB][16];           // ph2
    __shared__ float red[16];
    __shared__ float bcast;
    __shared__ unsigned int s_r0;

    int tid = threadIdx.x;
    int bx = blockIdx.x;
    int warp = tid >> 5, lane = tid & 31;

    // ========= Phase 1: q0[b,e] = Wq[e,:]·x[b,0,:] + bq[e]  (atomic) ======
    // 2048 tasks (e, half-row) over blocks 0..127. g_q0 pre-zeroed.
    if (bx < 128) {
        // stage x[b,0,:]: 2048 float4 over 512 threads (MLP 4)
#pragma unroll
        for (int j = 0; j < 4; j++) {
            int idx = tid + 512 * j;
            int b = idx >> 8, d4 = idx & 255;
            buf4[idx] = ((const float4*)x)[(size_t)b * (NN * DIM / 4) + d4];
        }
        __syncthreads();

        int gw = bx * 16 + warp;      // 0..2047
        int e = gw >> 1;
        int h = gw & 1;
        int base = h * 128;           // float4 offset within row
        const float4* wrow4 = (const float4*)Wq + (size_t)e * 256 + base;

        float acc[BB];
#pragma unroll
        for (int b = 0; b < BB; b++) acc[b] = 0.0f;
#pragma unroll
        for (int j = 0; j < 4; j++) {
            int i = lane + 32 * j;
            float4 w4 = wrow4[i];
#pragma unroll
            for (int b = 0; b < BB; b++) {
                float4 x4 = buf4[b * 256 + base + i];
                acc[b] += w4.x * x4.x + w4.y * x4.y + w4.z * x4.z + w4.w * x4.w;
            }
        }
#pragma unroll
        for (int b = 0; b < BB; b++) acc[b] = warp_sum(acc[b]);
        if (lane == 0) {
            float bias = (h == 0) ? bq[e] : 0.0f;
#pragma unroll
            for (int b = 0; b < BB; b++)
                atomicAdd(&g_q0[b * DIM + e], acc[b] + bias);
        }
    }

    grid_barrier(&g_b1);

    // ========= Phase 2: v[b,d] += q0[b,e-chunk]·Wk[e-chunk,d] =============
    // 128 blocks: 64 e-chunks (16 e) x 2 d-halves (512 d). g_v pre-zeroed.
    if (bx < 128) {
        int e0 = (bx >> 1) * 16;
        int d = (bx & 1) * 512 + tid;
        if (tid < BB * 16) {
            int b = tid >> 4, j = tid & 15;
            qs[b][j] = __ldcg(&g_q0[b * DIM + e0 + j]);
        }
        __syncthreads();

        float vacc[BB];
#pragma unroll
        for (int b = 0; b < BB; b++) vacc[b] = 0.0f;
#pragma unroll
        for (int j = 0; j < 16; j++) {
            float w = __ldcs(&Wk[(size_t)(e0 + j) * DIM + d]);
#pragma unroll
            for (int b = 0; b < BB; b++) vacc[b] += qs[b][j] * w;
        }
#pragma unroll
        for (int b = 0; b < BB; b++) atomicAdd(&g_v[b * DIM + d], vacc[b]);
    }

    grid_barrier(&g_b2);

    // ========= Phase 3: scores[r] = x[r,:]·v[b(r),:]  (dynamic chunks) ====
#pragma unroll
    for (int j = 0; j < 4; j++) {
        int idx = tid + 512 * j;
        buf4[idx] = __ldcg((const float4*)g_v + idx);
    }
    __syncthreads();

    for (;;) {
        if (tid == 0) s_r0 = atomicAdd(&g_row, (unsigned)CHUNK);
        __syncthreads();
        unsigned int r0 = s_r0;
        if (r0 >= (unsigned)TOTAL_ROWS) break;
#pragma unroll
        for (int k = 0; k < 2; k++) {
            int r = (int)r0 + k * 16 + warp;
            int b = r >> 12;
            const float4* xr4 = (const float4*)x + (size_t)r * 256;
            float a0 = 0.0f, a1 = 0.0f;
#pragma unroll
            for (int j = 0; j < 8; j += 2) {
                float4 u0 = __ldcs(&xr4[lane + 32 * j]);
                float4 u1 = __ldcs(&xr4[lane + 32 * (j + 1)]);
                float4 v0 = buf4[b * 256 + lane + 32 * j];
                float4 v1 = buf4[b * 256 + lane + 32 * (j + 1)];
                a0 += u0.x * v0.x + u0.y * v0.y + u0.z * v0.z + u0.w * v0.w;
                a1 += u1.x * v1.x + u1.y * v1.y + u1.z * v1.z + u1.w * v1.w;
            }
            float acc = warp_sum(a0 + a1);
            if (lane == 0) g_scores[r] = acc;
        }
        __syncthreads();
    }

    grid_barrier(&g_b3);

    // ========= End-of-run housekeeping (for next replay) ==================
    if (bx >= 8 && bx < 24) {
        g_v[(bx - 8) * 512 + tid] = 0.0f;
    } else if (bx >= 24 && bx < 40) {
        g_q0[(bx - 24) * 512 + tid] = 0.0f;
    } else if (bx == 40 && tid == 0) {
        g_row = 0u;
    }

    // ========= Phase 4: softmax, blocks 0..7 ==============================
    if (bx >= 8) return;
    int sb = bx;

    float s[8];
#pragma unroll
    for (int i = 0; i < 8; i++)
        s[i] = __ldcg(&g_scores[sb * NN + tid + i * 512]);

    float m = s[0];
#pragma unroll
    for (int i = 1; i < 8; i++) m = fmaxf(m, s[i]);
#pragma unroll
    for (int off = 16; off > 0; off >>= 1)
        m = fmaxf(m, __shfl_down_sync(0xFFFFFFFFu, m, off));
    if (lane == 0) red[warp] = m;
    __syncthreads();
    if (warp == 0) {
        float v = (lane < 16) ? red[lane] : -1e30f;
#pragma unroll
        for (int off = 16; off > 0; off >>= 1)
            v = fmaxf(v, __shfl_down_sync(0xFFFFFFFFu, v, off));
        if (lane == 0) bcast = v;
    }
    __syncthreads();
    float M = bcast;

    float e[8];
    float local = 0.0f;
#pragma unroll
    for (int i = 0; i < 8; i++) {
        e[i] = expf(s[i] - M);
        local += e[i];
    }
    local = warp_sum(local);
    if (lane == 0) red[warp] = local;
    __syncthreads();
    if (warp == 0) {
        float v = (lane < 16) ? red[lane] : 0.0f;
        v = warp_sum(v);
        if (lane == 0) bcast = v;
    }
    __syncthreads();
    float inv = 1.0f / bcast;

#pragma unroll
    for (int i = 0; i < 8; i++)
        out[sb * NN + tid + i * 512] = e[i] * inv;
}

extern "C" void kernel_launch(void* const* d_in, const int* in_sizes, int n_in,
                              void* d_out, int out_size) {
    const float* x  = (const float*)d_in[0];
    const float* Wq = (const float*)d_in[1];
    const float* bq = (const float*)d_in[2];
    const float* Wk = (const float*)d_in[3];
    // bk (d_in[4]) is mathematically dead: it shifts every score in a row by
    // the same constant, which cancels in softmax.
    float* out = (float*)d_out;

    k_fused<<<GRID, 512>>>(x, Wq, bq, Wk, out);
}

// round 11
// speedup vs baseline: 2.2303x; 1.1070x over previous
#include <cuda_runtime.h>
#include <math.h>

#define BB 8
#define NN 4096
#define DIM 1024
#define GRID 296            // 148 SMs x 2 CTAs, all resident
#define TOTAL_ROWS (BB * NN)
#define CHUNK 32            // rows per dynamic grab
#define PF_ROWS 8064        // rows L2-prefetched during prepass (31.5 MB)

// Scratch (no allocation allowed). Zero at load; re-zeroed at end of each run.
__device__ float g_q0[BB * DIM];
__device__ float g_v[BB * DIM];
__device__ float g_scores[BB * NN];
__device__ unsigned int g_b1, g_b2, g_b3;  // monotonic barrier counters
__device__ unsigned int g_row;             // phase-3 ticket (reset at end)

__device__ __forceinline__ float warp_sum(float v) {
#pragma unroll
    for (int off = 16; off > 0; off >>= 1)
        v += __shfl_down_sync(0xFFFFFFFFu, v, off);
    return v;
}

// Monotonic grid barrier: safe across graph replays (counter never resets).
__device__ __forceinline__ void grid_barrier(unsigned int* ctr) {
    __shared__ unsigned int s_tk;
    __threadfence();
    __syncthreads();
    if (threadIdx.x == 0) s_tk = atomicAdd(ctr, 1u);
    __syncthreads();
    unsigned int target = (s_tk / GRID + 1u) * GRID;
    if (threadIdx.x == 0) {
        while (atomicAdd(ctr, 0u) < target) __nanosleep(32);
    }
    __syncthreads();
    __threadfence();
}

// One row-dot: x[r,:] (1024 f32) . v (in smem). LCG: L2-resident path.
template <bool LCG>
__device__ __forceinline__ float row_dot(const float4* __restrict__ xr4,
                                         const float4* __restrict__ vsm,
                                         int lane) {
    float a0 = 0.0f, a1 = 0.0f;
#pragma unroll
    for (int j = 0; j < 8; j += 2) {
        float4 u0 = LCG ? __ldcg(&xr4[lane + 32 * j])
                        : __ldcs(&xr4[lane + 32 * j]);
        float4 u1 = LCG ? __ldcg(&xr4[lane + 32 * (j + 1)])
                        : __ldcs(&xr4[lane + 32 * (j + 1)]);
        float4 v0 = vsm[lane + 32 * j];
        float4 v1 = vsm[lane + 32 * (j + 1)];
        a0 += u0.x * v0.x + u0.y * v0.y + u0.z * v0.z + u0.w * v0.w;
        a1 += u1.x * v1.x + u1.y * v1.y + u1.z * v1.z + u1.w * v1.w;
    }
    return a0 + a1;
}

__global__ void __launch_bounds__(512, 2)
k_fused(const float* __restrict__ x, const float* __restrict__ Wq,
        const float* __restrict__ bq, const float* __restrict__ Wk,
        float* __restrict__ out) {
    __shared__ float4 buf4[BB * DIM / 4];  // 32 KB: xs (ph1) / vs (ph3)
    __shared__ float qs[BB][16];           // ph2
    __shared__ float red[16];
    __shared__ float bcast;
    __shared__ unsigned int s_r0;

    int tid = threadIdx.x;
    int bx = blockIdx.x;
    int warp = tid >> 5, lane = tid & 31;

    // ========= Phase 1 (blocks 0..127): q0 = Wq@x0 + bq  (atomic halves) ==
    // Blocks 128..295: fire-and-forget L2 prefetch of x rows 0..PF_ROWS-1.
    if (bx < 128) {
        // stage x[b,0,:]: 2048 float4 over 512 threads (MLP 4)
#pragma unroll
        for (int j = 0; j < 4; j++) {
            int idx = tid + 512 * j;
            int b = idx >> 8, d4 = idx & 255;
            buf4[idx] = ((const float4*)x)[(size_t)b * (NN * DIM / 4) + d4];
        }
        __syncthreads();

        int gw = bx * 16 + warp;      // 0..2047
        int e = gw >> 1;
        int h = gw & 1;
        int base = h * 128;           // float4 offset within row
        const float4* wrow4 = (const float4*)Wq + (size_t)e * 256 + base;

        float acc[BB];
#pragma unroll
        for (int b = 0; b < BB; b++) acc[b] = 0.0f;
#pragma unroll
        for (int j = 0; j < 4; j++) {
            int i = lane + 32 * j;
            float4 w4 = wrow4[i];
#pragma unroll
            for (int b = 0; b < BB; b++) {
                float4 x4 = buf4[b * 256 + base + i];
                acc[b] += w4.x * x4.x + w4.y * x4.y + w4.z * x4.z + w4.w * x4.w;
            }
        }
#pragma unroll
        for (int b = 0; b < BB; b++) acc[b] = warp_sum(acc[b]);
        if (lane == 0) {
            float bias = (h == 0) ? bq[e] : 0.0f;
#pragma unroll
            for (int b = 0; b < BB; b++)
                atomicAdd(&g_q0[b * DIM + e], acc[b] + bias);
        }
    } else {
        // 168 blocks x 48 rows = 8064 rows = 31.5 MB into L2.
        // One warp-instruction prefetches one 4 KB row (32 lanes x 128 B).
        int pb = bx - 128;                 // 0..167
        int r0 = pb * 48 + warp * 3;       // each warp: 3 rows
        const char* xb = (const char*)x;
#pragma unroll
        for (int k = 0; k < 3; k++) {
            size_t off = ((size_t)(r0 + k) << 12) + ((size_t)lane << 7);
            asm volatile("prefetch.global.L2 [%0];" :: "l"(xb + off));
        }
    }

    grid_barrier(&g_b1);

    // ========= Phase 2: v[b,d] += q0[b,e-chunk]·Wk[e-chunk,d] =============
    // 128 blocks: 64 e-chunks (16 e) x 2 d-halves (512 d). g_v pre-zeroed.
    if (bx < 128) {
        int e0 = (bx >> 1) * 16;
        int d = (bx & 1) * 512 + tid;
        if (tid < BB * 16) {
            int b = tid >> 4, j = tid & 15;
            qs[b][j] = __ldcg(&g_q0[b * DIM + e0 + j]);
        }
        __syncthreads();

        float vacc[BB];
#pragma unroll
        for (int b = 0; b < BB; b++) vacc[b] = 0.0f;
#pragma unroll
        for (int j = 0; j < 16; j++) {
            float w = __ldcs(&Wk[(size_t)(e0 + j) * DIM + d]);
#pragma unroll
            for (int b = 0; b < BB; b++) vacc[b] += qs[b][j] * w;
        }
#pragma unroll
        for (int b = 0; b < BB; b++) atomicAdd(&g_v[b * DIM + d], vacc[b]);
    }

    grid_barrier(&g_b2);

    // ========= Phase 3: scores[r] = x[r,:]·v[b(r),:]  (dynamic chunks) ====
#pragma unroll
    for (int j = 0; j < 4; j++) {
        int idx = tid + 512 * j;
        buf4[idx] = __ldcg((const float4*)g_v + idx);
    }
    __syncthreads();

    for (;;) {
        if (tid == 0) s_r0 = atomicAdd(&g_row, (unsigned)CHUNK);
        __syncthreads();
        unsigned int r0 = s_r0;
        if (r0 >= (unsigned)TOTAL_ROWS) break;
        bool inL2 = (r0 < (unsigned)PF_ROWS);  // PF_ROWS is CHUNK-aligned
#pragma unroll
        for (int k = 0; k < 2; k++) {
            int r = (int)r0 + k * 16 + warp;
            int b = r >> 12;
            const float4* xr4 = (const float4*)x + (size_t)r * 256;
            const float4* vsm = buf4 + b * 256;
            float acc = inL2 ? row_dot<true>(xr4, vsm, lane)
                             : row_dot<false>(xr4, vsm, lane);
            acc = warp_sum(acc);
            if (lane == 0) g_scores[r] = acc;
        }
        __syncthreads();
    }

    grid_barrier(&g_b3);

    // ========= End-of-run housekeeping (for next replay) ==================
    if (bx >= 8 && bx < 24) {
        g_v[(bx - 8) * 512 + tid] = 0.0f;
    } else if (bx >= 24 && bx < 40) {
        g_q0[(bx - 24) * 512 + tid] = 0.0f;
    } else if (bx == 40 && tid == 0) {
        g_row = 0u;
    }

    // ========= Phase 4: softmax, blocks 0..7 ==============================
    if (bx >= 8) return;
    int sb = bx;

    float s[8];
#pragma unroll
    for (int i = 0; i < 8; i++)
        s[i] = __ldcg(&g_scores[sb * NN + tid + i * 512]);

    float m = s[0];
#pragma unroll
    for (int i = 1; i < 8; i++) m = fmaxf(m, s[i]);
#pragma unroll
    for (int off = 16; off > 0; off >>= 1)
        m = fmaxf(m, __shfl_down_sync(0xFFFFFFFFu, m, off));
    if (lane == 0) red[warp] = m;
    __syncthreads();
    if (warp == 0) {
        float v = (lane < 16) ? red[lane] : -1e30f;
#pragma unroll
        for (int off = 16; off > 0; off >>= 1)
            v = fmaxf(v, __shfl_down_sync(0xFFFFFFFFu, v, off));
        if (lane == 0) bcast = v;
    }
    __syncthreads();
    float M = bcast;

    float e[8];
    float local = 0.0f;
#pragma unroll
    for (int i = 0; i < 8; i++) {
        e[i] = expf(s[i] - M);
        local += e[i];
    }
    local = warp_sum(local);
    if (lane == 0) red[warp] = local;
    __syncthreads();
    if (warp == 0) {
        float v = (lane < 16) ? red[lane] : 0.0f;
        v = warp_sum(v);
        if (lane == 0) bcast = v;
    }
    __syncthreads();
    float inv = 1.0f / bcast;

#pragma unroll
    for (int i = 0; i < 8; i++)
        out[sb * NN + tid + i * 512] = e[i] * inv;
}

extern "C" void kernel_launch(void* const* d_in, const int* in_sizes, int n_in,
                              void* d_out, int out_size) {
    const float* x  = (const float*)d_in[0];
    const float* Wq = (const float*)d_in[1];
    const float* bq = (const float*)d_in[2];
    const float* Wk = (const float*)d_in[3];
    // bk (d_in[4]) is mathematically dead: it shifts every score in a row by
    // the same constant, which cancels in softmax.
    float* out = (float*)d_out;

    k_fused<<<GRID, 512>>>(x, Wq, bq, Wk, out);
}